// round 3
// baseline (speedup 1.0000x reference)
#include <cuda_runtime.h>
#include <math.h>

#define NB   8
#define NSEQ 1024
#define CDIM 768
#define NH   12
#define HD   64

// Scratch (device globals: allocation-free per harness rules)
__device__ float g_qkv[(size_t)NB * NSEQ * 3 * CDIM];     // 8*1024*2304  = 75.5 MB
__device__ float g_attn[(size_t)NB * NH * NSEQ * NSEQ];   // 96*1024*1024 = 402 MB
__device__ float g_o2[(size_t)NB * NSEQ * CDIM];          // 8*1024*768   = 25 MB

// ---------------------------------------------------------------------------
// Generic tiled SGEMM: C[M,N] = alpha * A[M,K] @ B'[K,N] (+ bias[n])
//   TRANSB=false: B stored [K,N] row-major (ldb = N-stride)
//   TRANSB=true : B stored [N,K] row-major (ldb = K-stride)  (i.e. C = A @ B^T)
// Batched via blockIdx.z with split strides: z -> (zo = z/zdiv, zi = z%zdiv)
// ---------------------------------------------------------------------------
template<int BM, int BN, int BK, int TM, int TN, bool TRANSB, bool BIAS>
__global__ __launch_bounds__(256) void gemm_kernel(
    const float* __restrict__ A, const float* __restrict__ Bm,
    float* __restrict__ C, const float* __restrict__ bias,
    int M, int Nn, int K, int lda, int ldb, int ldc,
    int zdiv,
    long long sAo, long long sAi,
    long long sBo, long long sBi,
    long long sCo, long long sCi,
    float alpha)
{
    static_assert(BK == 16, "loader assumes BK==16");
    __shared__ float As[BM][BK + 1];   // +1 pad: conflict-free col-wise reads
    __shared__ float Bs[BK][BN + 4];   // +4 pad: tames TRANSB store conflicts

    {
        int z  = blockIdx.z;
        int zo = z / zdiv;
        int zi = z - zo * zdiv;
        A  += zo * sAo + zi * sAi;
        Bm += zo * sBo + zi * sBi;
        C  += zo * sCo + zi * sCi;
    }

    const int tid = threadIdx.x;
    const int m0  = blockIdx.y * BM;
    const int n0  = blockIdx.x * BN;
    const int tx  = tid & 15;       // 16 thread cols
    const int ty  = tid >> 4;       // 16 thread rows

    float acc[TM][TN];
    #pragma unroll
    for (int i = 0; i < TM; i++)
        #pragma unroll
        for (int j = 0; j < TN; j++)
            acc[i][j] = 0.f;

    for (int k0 = 0; k0 < K; k0 += BK) {
        // ---- load A tile (BM x BK), coalesced along k ----
        #pragma unroll
        for (int i = 0; i < (BM * BK) / 256; i++) {
            int idx = tid + i * 256;
            int m = idx >> 4;          // idx / BK
            int k = idx & 15;          // idx % BK
            As[m][k] = A[(long long)(m0 + m) * lda + (k0 + k)];
        }
        // ---- load B tile (BK x BN) ----
        if (TRANSB) {
            #pragma unroll
            for (int i = 0; i < (BN * BK) / 256; i++) {
                int idx = tid + i * 256;
                int n = idx >> 4;
                int k = idx & 15;
                Bs[k][n] = Bm[(long long)(n0 + n) * ldb + (k0 + k)];
            }
        } else {
            #pragma unroll
            for (int i = 0; i < (BN * BK) / 256; i++) {
                int idx = tid + i * 256;
                int k = idx / BN;
                int n = idx - k * BN;
                Bs[k][n] = Bm[(long long)(k0 + k) * ldb + (n0 + n)];
            }
        }
        __syncthreads();

        // ---- compute 8x4 per-thread outer products ----
        #pragma unroll
        for (int k = 0; k < BK; k++) {
            float a[TM], b[TN];
            #pragma unroll
            for (int i = 0; i < TM; i++) a[i] = As[ty * TM + i][k];
            #pragma unroll
            for (int j = 0; j < TN; j++) b[j] = Bs[k][tx * TN + j];
            #pragma unroll
            for (int i = 0; i < TM; i++)
                #pragma unroll
                for (int j = 0; j < TN; j++)
                    acc[i][j] += a[i] * b[j];
        }
        __syncthreads();
    }

    // ---- epilogue ----
    #pragma unroll
    for (int i = 0; i < TM; i++) {
        int m = m0 + ty * TM + i;
        #pragma unroll
        for (int j = 0; j < TN; j++) {
            int n = n0 + tx * TN + j;
            float v = acc[i][j] * alpha;
            if (BIAS) v += bias[n];
            C[(long long)m * ldc + n] = v;
        }
    }
}

// ---------------------------------------------------------------------------
// Fused: attn_row = softmax(scores_row * scale + bias_table[rel_index_row])
// one block (256 threads) per (b,h,n) row of 1024 elements
// ---------------------------------------------------------------------------
__global__ __launch_bounds__(256) void softmax_bias_kernel(
    float* __restrict__ attn,
    const float* __restrict__ bias_table,
    const int* __restrict__ rel_index,
    float scale)
{
    const int r  = blockIdx.x;            // r = bh*NSEQ + n
    const int n  = r & (NSEQ - 1);
    const int bh = r >> 10;
    const int h  = bh % NH;

    float* row = attn + (long long)r * NSEQ;
    const int* ridx = rel_index + (long long)n * NSEQ;
    const int tid = threadIdx.x;

    float v[4];
    float mx = -INFINITY;
    #pragma unroll
    for (int i = 0; i < 4; i++) {
        int m = tid + i * 256;
        float s = row[m] * scale + bias_table[ridx[m] * NH + h];
        v[i] = s;
        mx = fmaxf(mx, s);
    }

    __shared__ float red[8];
    #pragma unroll
    for (int off = 16; off > 0; off >>= 1)
        mx = fmaxf(mx, __shfl_xor_sync(0xffffffffu, mx, off));
    if ((tid & 31) == 0) red[tid >> 5] = mx;
    __syncthreads();
    mx = fmaxf(fmaxf(fmaxf(red[0], red[1]), fmaxf(red[2], red[3])),
               fmaxf(fmaxf(red[4], red[5]), fmaxf(red[6], red[7])));

    float sum = 0.f;
    #pragma unroll
    for (int i = 0; i < 4; i++) { v[i] = __expf(v[i] - mx); sum += v[i]; }
    #pragma unroll
    for (int off = 16; off > 0; off >>= 1)
        sum += __shfl_xor_sync(0xffffffffu, sum, off);
    __syncthreads();
    if ((tid & 31) == 0) red[tid >> 5] = sum;
    __syncthreads();
    sum = red[0] + red[1] + red[2] + red[3] + red[4] + red[5] + red[6] + red[7];

    float inv = 1.f / sum;
    #pragma unroll
    for (int i = 0; i < 4; i++)
        row[tid + i * 256] = v[i] * inv;
}

// ---------------------------------------------------------------------------
extern "C" void kernel_launch(void* const* d_in, const int* in_sizes, int n_in,
                              void* d_out, int out_size)
{
    const float* x          = (const float*)d_in[0];
    const float* qkv_w      = (const float*)d_in[1];
    const float* proj_w     = (const float*)d_in[2];
    const float* proj_b     = (const float*)d_in[3];
    const float* bias_table = (const float*)d_in[4];
    const int*   rel_index  = (const int*)d_in[5];
    float* out = (float*)d_out;

    float *qkv, *attn, *o2;
    cudaGetSymbolAddress((void**)&qkv,  g_qkv);
    cudaGetSymbolAddress((void**)&attn, g_attn);
    cudaGetSymbolAddress((void**)&o2,   g_o2);

    const dim3 blk(256);
    const long long sQKV = (long long)NSEQ * 3 * CDIM;    // per-batch qkv row stride
    const long long sATT = (long long)NSEQ * NSEQ;        // per-(b,h) attn stride

    // 1) qkv = x @ qkv_w : [8192,2304] = [8192,768] @ [768,2304]
    gemm_kernel<128, 64, 16, 8, 4, false, false>
        <<<dim3(3 * CDIM / 64, NB * NSEQ / 128, 1), blk>>>(
        x, qkv_w, qkv, nullptr,
        NB * NSEQ, 3 * CDIM, CDIM, CDIM, 3 * CDIM, 3 * CDIM,
        1, 0, 0, 0, 0, 0, 0, 1.f);

    // 2) S[bh] = Q[bh] @ K[bh]^T : 96 x [1024,1024,64]
    gemm_kernel<128, 64, 16, 8, 4, true, false>
        <<<dim3(NSEQ / 64, NSEQ / 128, NB * NH), blk>>>(
        qkv /*Q at col 0*/, qkv + CDIM /*K at col 768*/, attn, nullptr,
        NSEQ, NSEQ, HD, 3 * CDIM, 3 * CDIM, NSEQ,
        NH, sQKV, HD, sQKV, HD, (long long)NH * sATT, sATT, 1.f);

    // 3) softmax(S*scale + rel_bias)
    softmax_bias_kernel<<<NB * NH * NSEQ, 256>>>(attn, bias_table, rel_index, 0.125f);

    // 4) O2[bh] = P[bh] @ V[bh] : 96 x [1024,64,1024] -> packed [8192,768]
    gemm_kernel<128, 64, 16, 8, 4, false, false>
        <<<dim3(HD / 64, NSEQ / 128, NB * NH), blk>>>(
        attn, qkv + 2 * CDIM /*V at col 1536*/, o2, nullptr,
        NSEQ, HD, NSEQ, NSEQ, 3 * CDIM, CDIM,
        NH, (long long)NH * sATT, sATT, sQKV, HD, (long long)NSEQ * CDIM, HD, 1.f);

    // 5) out = O2 @ proj_w + proj_b : [8192,768]
    gemm_kernel<128, 64, 16, 8, 4, false, true>
        <<<dim3(CDIM / 64, NB * NSEQ / 128, 1), blk>>>(
        o2, proj_w, out, proj_b,
        NB * NSEQ, CDIM, CDIM, CDIM, CDIM, CDIM,
        1, 0, 0, 0, 0, 0, 0, 1.f);
}

// round 4
// speedup vs baseline: 1.0002x; 1.0002x over previous
#include <cuda_runtime.h>
#include <math.h>

#define NB   8
#define NSEQ 1024
#define CDIM 768
#define NH   12
#define HD   64

// Scratch (device globals: allocation-free per harness rules)
__device__ float g_qkv[(size_t)NB * NSEQ * 3 * CDIM];     // 8*1024*2304  = 75.5 MB
__device__ float g_attn[(size_t)NB * NH * NSEQ * NSEQ];   // 96*1024*1024 = 402 MB
__device__ float g_o2[(size_t)NB * NSEQ * CDIM];          // 8*1024*768   = 25 MB

// ---------------------------------------------------------------------------
// Generic tiled SGEMM: C[M,N] = alpha * A[M,K] @ B'[K,N] (+ bias[n])
//   TRANSB=false: B stored [K,N] row-major (ldb = N-stride)
//   TRANSB=true : B stored [N,K] row-major (ldb = K-stride)  (i.e. C = A @ B^T)
// Batched via blockIdx.z with split strides: z -> (zo = z/zdiv, zi = z%zdiv)
// ---------------------------------------------------------------------------
template<int BM, int BN, int BK, int TM, int TN, bool TRANSB, bool BIAS>
__global__ __launch_bounds__(256) void gemm_kernel(
    const float* __restrict__ A, const float* __restrict__ Bm,
    float* __restrict__ C, const float* __restrict__ bias,
    int M, int Nn, int K, int lda, int ldb, int ldc,
    int zdiv,
    long long sAo, long long sAi,
    long long sBo, long long sBi,
    long long sCo, long long sCi,
    float alpha)
{
    static_assert(BK == 16, "loader assumes BK==16");
    __shared__ float As[BM][BK + 1];   // +1 pad: conflict-free col-wise reads
    __shared__ float Bs[BK][BN + 4];   // +4 pad: tames TRANSB store conflicts

    {
        int z  = blockIdx.z;
        int zo = z / zdiv;
        int zi = z - zo * zdiv;
        A  += zo * sAo + zi * sAi;
        Bm += zo * sBo + zi * sBi;
        C  += zo * sCo + zi * sCi;
    }

    const int tid = threadIdx.x;
    const int m0  = blockIdx.y * BM;
    const int n0  = blockIdx.x * BN;
    const int tx  = tid & 15;       // 16 thread cols
    const int ty  = tid >> 4;       // 16 thread rows

    float acc[TM][TN];
    #pragma unroll
    for (int i = 0; i < TM; i++)
        #pragma unroll
        for (int j = 0; j < TN; j++)
            acc[i][j] = 0.f;

    for (int k0 = 0; k0 < K; k0 += BK) {
        // ---- load A tile (BM x BK), coalesced along k ----
        #pragma unroll
        for (int i = 0; i < (BM * BK) / 256; i++) {
            int idx = tid + i * 256;
            int m = idx >> 4;          // idx / BK
            int k = idx & 15;          // idx % BK
            As[m][k] = A[(long long)(m0 + m) * lda + (k0 + k)];
        }
        // ---- load B tile (BK x BN) ----
        if (TRANSB) {
            #pragma unroll
            for (int i = 0; i < (BN * BK) / 256; i++) {
                int idx = tid + i * 256;
                int n = idx >> 4;
                int k = idx & 15;
                Bs[k][n] = Bm[(long long)(n0 + n) * ldb + (k0 + k)];
            }
        } else {
            #pragma unroll
            for (int i = 0; i < (BN * BK) / 256; i++) {
                int idx = tid + i * 256;
                int k = idx / BN;
                int n = idx - k * BN;
                Bs[k][n] = Bm[(long long)(k0 + k) * ldb + (n0 + n)];
            }
        }
        __syncthreads();

        // ---- compute 8x4 per-thread outer products ----
        #pragma unroll
        for (int k = 0; k < BK; k++) {
            float a[TM], b[TN];
            #pragma unroll
            for (int i = 0; i < TM; i++) a[i] = As[ty * TM + i][k];
            #pragma unroll
            for (int j = 0; j < TN; j++) b[j] = Bs[k][tx * TN + j];
            #pragma unroll
            for (int i = 0; i < TM; i++)
                #pragma unroll
                for (int j = 0; j < TN; j++)
                    acc[i][j] += a[i] * b[j];
        }
        __syncthreads();
    }

    // ---- epilogue ----
    #pragma unroll
    for (int i = 0; i < TM; i++) {
        int m = m0 + ty * TM + i;
        #pragma unroll
        for (int j = 0; j < TN; j++) {
            int n = n0 + tx * TN + j;
            float v = acc[i][j] * alpha;
            if (BIAS) v += bias[n];
            C[(long long)m * ldc + n] = v;
        }
    }
}

// ---------------------------------------------------------------------------
// Fused: attn_row = softmax(scores_row * scale + bias_table[rel_index_row])
// one block (256 threads) per (b,h,n) row of 1024 elements
// ---------------------------------------------------------------------------
__global__ __launch_bounds__(256) void softmax_bias_kernel(
    float* __restrict__ attn,
    const float* __restrict__ bias_table,
    const int* __restrict__ rel_index,
    float scale)
{
    const int r  = blockIdx.x;            // r = bh*NSEQ + n
    const int n  = r & (NSEQ - 1);
    const int bh = r >> 10;
    const int h  = bh % NH;

    float* row = attn + (long long)r * NSEQ;
    const int* ridx = rel_index + (long long)n * NSEQ;
    const int tid = threadIdx.x;

    float v[4];
    float mx = -INFINITY;
    #pragma unroll
    for (int i = 0; i < 4; i++) {
        int m = tid + i * 256;
        float s = row[m] * scale + bias_table[ridx[m] * NH + h];
        v[i] = s;
        mx = fmaxf(mx, s);
    }

    __shared__ float red[8];
    #pragma unroll
    for (int off = 16; off > 0; off >>= 1)
        mx = fmaxf(mx, __shfl_xor_sync(0xffffffffu, mx, off));
    if ((tid & 31) == 0) red[tid >> 5] = mx;
    __syncthreads();
    mx = fmaxf(fmaxf(fmaxf(red[0], red[1]), fmaxf(red[2], red[3])),
               fmaxf(fmaxf(red[4], red[5]), fmaxf(red[6], red[7])));

    float sum = 0.f;
    #pragma unroll
    for (int i = 0; i < 4; i++) { v[i] = __expf(v[i] - mx); sum += v[i]; }
    #pragma unroll
    for (int off = 16; off > 0; off >>= 1)
        sum += __shfl_xor_sync(0xffffffffu, sum, off);
    __syncthreads();
    if ((tid & 31) == 0) red[tid >> 5] = sum;
    __syncthreads();
    sum = red[0] + red[1] + red[2] + red[3] + red[4] + red[5] + red[6] + red[7];

    float inv = 1.f / sum;
    #pragma unroll
    for (int i = 0; i < 4; i++)
        row[tid + i * 256] = v[i] * inv;
}

// ---------------------------------------------------------------------------
extern "C" void kernel_launch(void* const* d_in, const int* in_sizes, int n_in,
                              void* d_out, int out_size)
{
    const float* x          = (const float*)d_in[0];
    const float* qkv_w      = (const float*)d_in[1];
    const float* proj_w     = (const float*)d_in[2];
    const float* proj_b     = (const float*)d_in[3];
    const float* bias_table = (const float*)d_in[4];
    const int*   rel_index  = (const int*)d_in[5];
    float* out = (float*)d_out;

    float *qkv, *attn, *o2;
    cudaGetSymbolAddress((void**)&qkv,  g_qkv);
    cudaGetSymbolAddress((void**)&attn, g_attn);
    cudaGetSymbolAddress((void**)&o2,   g_o2);

    const dim3 blk(256);
    const long long sQKV = (long long)NSEQ * 3 * CDIM;    // per-batch qkv row stride
    const long long sATT = (long long)NSEQ * NSEQ;        // per-(b,h) attn stride

    // 1) qkv = x @ qkv_w : [8192,2304] = [8192,768] @ [768,2304]
    gemm_kernel<128, 64, 16, 8, 4, false, false>
        <<<dim3(3 * CDIM / 64, NB * NSEQ / 128, 1), blk>>>(
        x, qkv_w, qkv, nullptr,
        NB * NSEQ, 3 * CDIM, CDIM, CDIM, 3 * CDIM, 3 * CDIM,
        1, 0, 0, 0, 0, 0, 0, 1.f);

    // 2) S[bh] = Q[bh] @ K[bh]^T : 96 x [1024,1024,64]
    gemm_kernel<128, 64, 16, 8, 4, true, false>
        <<<dim3(NSEQ / 64, NSEQ / 128, NB * NH), blk>>>(
        qkv /*Q at col 0*/, qkv + CDIM /*K at col 768*/, attn, nullptr,
        NSEQ, NSEQ, HD, 3 * CDIM, 3 * CDIM, NSEQ,
        NH, sQKV, HD, sQKV, HD, (long long)NH * sATT, sATT, 1.f);

    // 3) softmax(S*scale + rel_bias)
    softmax_bias_kernel<<<NB * NH * NSEQ, 256>>>(attn, bias_table, rel_index, 0.125f);

    // 4) O2[bh] = P[bh] @ V[bh] : 96 x [1024,64,1024] -> packed [8192,768]
    gemm_kernel<128, 64, 16, 8, 4, false, false>
        <<<dim3(HD / 64, NSEQ / 128, NB * NH), blk>>>(
        attn, qkv + 2 * CDIM /*V at col 1536*/, o2, nullptr,
        NSEQ, HD, NSEQ, NSEQ, 3 * CDIM, CDIM,
        NH, (long long)NH * sATT, sATT, sQKV, HD, (long long)NSEQ * CDIM, HD, 1.f);

    // 5) out = O2 @ proj_w + proj_b : [8192,768]
    gemm_kernel<128, 64, 16, 8, 4, false, true>
        <<<dim3(CDIM / 64, NB * NSEQ / 128, 1), blk>>>(
        o2, proj_w, out, proj_b,
        NB * NSEQ, CDIM, CDIM, CDIM, CDIM, CDIM,
        1, 0, 0, 0, 0, 0, 0, 1.f);
}

// round 5
// speedup vs baseline: 1.0016x; 1.0015x over previous
#include <cuda_runtime.h>
#include <math.h>

#define NB   8
#define NSEQ 1024
#define CDIM 768
#define NH   12
#define HD   64

// Scratch (device globals: allocation-free per harness rules)
__device__ float g_qkv[(size_t)NB * NSEQ * 3 * CDIM];     // 8*1024*2304  = 75.5 MB
__device__ float g_attn[(size_t)NB * NH * NSEQ * NSEQ];   // 96*1024*1024 = 402 MB
__device__ float g_o2[(size_t)NB * NSEQ * CDIM];          // 8*1024*768   = 25 MB

// ---------------------------------------------------------------------------
// Generic tiled SGEMM: C[M,N] = alpha * A[M,K] @ B'[K,N] (+ bias[n])
//   TRANSB=false: B stored [K,N] row-major (ldb = N-stride)
//   TRANSB=true : B stored [N,K] row-major (ldb = K-stride)  (i.e. C = A @ B^T)
// Batched via blockIdx.z with split strides: z -> (zo = z/zdiv, zi = z%zdiv)
// ---------------------------------------------------------------------------
template<int BM, int BN, int BK, int TM, int TN, bool TRANSB, bool BIAS>
__global__ __launch_bounds__(256) void gemm_kernel(
    const float* __restrict__ A, const float* __restrict__ Bm,
    float* __restrict__ C, const float* __restrict__ bias,
    int M, int Nn, int K, int lda, int ldb, int ldc,
    int zdiv,
    long long sAo, long long sAi,
    long long sBo, long long sBi,
    long long sCo, long long sCi,
    float alpha)
{
    static_assert(BK == 16, "loader assumes BK==16");
    __shared__ float As[BM][BK + 1];   // +1 pad: conflict-free col-wise reads
    __shared__ float Bs[BK][BN + 4];   // +4 pad: tames TRANSB store conflicts

    {
        int z  = blockIdx.z;
        int zo = z / zdiv;
        int zi = z - zo * zdiv;
        A  += zo * sAo + zi * sAi;
        Bm += zo * sBo + zi * sBi;
        C  += zo * sCo + zi * sCi;
    }

    const int tid = threadIdx.x;
    const int m0  = blockIdx.y * BM;
    const int n0  = blockIdx.x * BN;
    const int tx  = tid & 15;       // 16 thread cols
    const int ty  = tid >> 4;       // 16 thread rows

    float acc[TM][TN];
    #pragma unroll
    for (int i = 0; i < TM; i++)
        #pragma unroll
        for (int j = 0; j < TN; j++)
            acc[i][j] = 0.f;

    for (int k0 = 0; k0 < K; k0 += BK) {
        // ---- load A tile (BM x BK), coalesced along k ----
        #pragma unroll
        for (int i = 0; i < (BM * BK) / 256; i++) {
            int idx = tid + i * 256;
            int m = idx >> 4;          // idx / BK
            int k = idx & 15;          // idx % BK
            As[m][k] = A[(long long)(m0 + m) * lda + (k0 + k)];
        }
        // ---- load B tile (BK x BN) ----
        if (TRANSB) {
            #pragma unroll
            for (int i = 0; i < (BN * BK) / 256; i++) {
                int idx = tid + i * 256;
                int n = idx >> 4;
                int k = idx & 15;
                Bs[k][n] = Bm[(long long)(n0 + n) * ldb + (k0 + k)];
            }
        } else {
            #pragma unroll
            for (int i = 0; i < (BN * BK) / 256; i++) {
                int idx = tid + i * 256;
                int k = idx / BN;
                int n = idx - k * BN;
                Bs[k][n] = Bm[(long long)(k0 + k) * ldb + (n0 + n)];
            }
        }
        __syncthreads();

        // ---- compute 8x4 per-thread outer products ----
        #pragma unroll
        for (int k = 0; k < BK; k++) {
            float a[TM], b[TN];
            #pragma unroll
            for (int i = 0; i < TM; i++) a[i] = As[ty * TM + i][k];
            #pragma unroll
            for (int j = 0; j < TN; j++) b[j] = Bs[k][tx * TN + j];
            #pragma unroll
            for (int i = 0; i < TM; i++)
                #pragma unroll
                for (int j = 0; j < TN; j++)
                    acc[i][j] += a[i] * b[j];
        }
        __syncthreads();
    }

    // ---- epilogue ----
    #pragma unroll
    for (int i = 0; i < TM; i++) {
        int m = m0 + ty * TM + i;
        #pragma unroll
        for (int j = 0; j < TN; j++) {
            int n = n0 + tx * TN + j;
            float v = acc[i][j] * alpha;
            if (BIAS) v += bias[n];
            C[(long long)m * ldc + n] = v;
        }
    }
}

// ---------------------------------------------------------------------------
// Fused: attn_row = softmax(scores_row * scale + bias_table[rel_index_row])
// one block (256 threads) per (b,h,n) row of 1024 elements
// ---------------------------------------------------------------------------
__global__ __launch_bounds__(256) void softmax_bias_kernel(
    float* __restrict__ attn,
    const float* __restrict__ bias_table,
    const int* __restrict__ rel_index,
    float scale)
{
    const int r  = blockIdx.x;            // r = bh*NSEQ + n
    const int n  = r & (NSEQ - 1);
    const int bh = r >> 10;
    const int h  = bh % NH;

    float* row = attn + (long long)r * NSEQ;
    const int* ridx = rel_index + (long long)n * NSEQ;
    const int tid = threadIdx.x;

    float v[4];
    float mx = -INFINITY;
    #pragma unroll
    for (int i = 0; i < 4; i++) {
        int m = tid + i * 256;
        float s = row[m] * scale + bias_table[ridx[m] * NH + h];
        v[i] = s;
        mx = fmaxf(mx, s);
    }

    __shared__ float red[8];
    #pragma unroll
    for (int off = 16; off > 0; off >>= 1)
        mx = fmaxf(mx, __shfl_xor_sync(0xffffffffu, mx, off));
    if ((tid & 31) == 0) red[tid >> 5] = mx;
    __syncthreads();
    mx = fmaxf(fmaxf(fmaxf(red[0], red[1]), fmaxf(red[2], red[3])),
               fmaxf(fmaxf(red[4], red[5]), fmaxf(red[6], red[7])));

    float sum = 0.f;
    #pragma unroll
    for (int i = 0; i < 4; i++) { v[i] = __expf(v[i] - mx); sum += v[i]; }
    #pragma unroll
    for (int off = 16; off > 0; off >>= 1)
        sum += __shfl_xor_sync(0xffffffffu, sum, off);
    __syncthreads();
    if ((tid & 31) == 0) red[tid >> 5] = sum;
    __syncthreads();
    sum = red[0] + red[1] + red[2] + red[3] + red[4] + red[5] + red[6] + red[7];

    float inv = 1.f / sum;
    #pragma unroll
    for (int i = 0; i < 4; i++)
        row[tid + i * 256] = v[i] * inv;
}

// ---------------------------------------------------------------------------
extern "C" void kernel_launch(void* const* d_in, const int* in_sizes, int n_in,
                              void* d_out, int out_size)
{
    const float* x          = (const float*)d_in[0];
    const float* qkv_w      = (const float*)d_in[1];
    const float* proj_w     = (const float*)d_in[2];
    const float* proj_b     = (const float*)d_in[3];
    const float* bias_table = (const float*)d_in[4];
    const int*   rel_index  = (const int*)d_in[5];
    float* out = (float*)d_out;

    float *qkv, *attn, *o2;
    cudaGetSymbolAddress((void**)&qkv,  g_qkv);
    cudaGetSymbolAddress((void**)&attn, g_attn);
    cudaGetSymbolAddress((void**)&o2,   g_o2);

    const dim3 blk(256);
    const long long sQKV = (long long)NSEQ * 3 * CDIM;    // per-batch qkv row stride
    const long long sATT = (long long)NSEQ * NSEQ;        // per-(b,h) attn stride

    // 1) qkv = x @ qkv_w : [8192,2304] = [8192,768] @ [768,2304]
    gemm_kernel<128, 64, 16, 8, 4, false, false>
        <<<dim3(3 * CDIM / 64, NB * NSEQ / 128, 1), blk>>>(
        x, qkv_w, qkv, nullptr,
        NB * NSEQ, 3 * CDIM, CDIM, CDIM, 3 * CDIM, 3 * CDIM,
        1, 0, 0, 0, 0, 0, 0, 1.f);

    // 2) S[bh] = Q[bh] @ K[bh]^T : 96 x [1024,1024,64]
    gemm_kernel<128, 64, 16, 8, 4, true, false>
        <<<dim3(NSEQ / 64, NSEQ / 128, NB * NH), blk>>>(
        qkv /*Q at col 0*/, qkv + CDIM /*K at col 768*/, attn, nullptr,
        NSEQ, NSEQ, HD, 3 * CDIM, 3 * CDIM, NSEQ,
        NH, sQKV, HD, sQKV, HD, (long long)NH * sATT, sATT, 1.f);

    // 3) softmax(S*scale + rel_bias)
    softmax_bias_kernel<<<NB * NH * NSEQ, 256>>>(attn, bias_table, rel_index, 0.125f);

    // 4) O2[bh] = P[bh] @ V[bh] : 96 x [1024,64,1024] -> packed [8192,768]
    gemm_kernel<128, 64, 16, 8, 4, false, false>
        <<<dim3(HD / 64, NSEQ / 128, NB * NH), blk>>>(
        attn, qkv + 2 * CDIM /*V at col 1536*/, o2, nullptr,
        NSEQ, HD, NSEQ, NSEQ, 3 * CDIM, CDIM,
        NH, (long long)NH * sATT, sATT, sQKV, HD, (long long)NSEQ * CDIM, HD, 1.f);

    // 5) out = O2 @ proj_w + proj_b : [8192,768]
    gemm_kernel<128, 64, 16, 8, 4, false, true>
        <<<dim3(CDIM / 64, NB * NSEQ / 128, 1), blk>>>(
        o2, proj_w, out, proj_b,
        NB * NSEQ, CDIM, CDIM, CDIM, CDIM, CDIM,
        1, 0, 0, 0, 0, 0, 0, 1.f);
}

// round 6
// speedup vs baseline: 1.0027x; 1.0011x over previous
#include <cuda_runtime.h>
#include <math.h>

#define NB   8
#define NSEQ 1024
#define CDIM 768
#define NH   12
#define HD   64

// Scratch (device globals: allocation-free per harness rules)
__device__ float g_qkv[(size_t)NB * NSEQ * 3 * CDIM];     // 8*1024*2304  = 75.5 MB
__device__ float g_attn[(size_t)NB * NH * NSEQ * NSEQ];   // 96*1024*1024 = 402 MB
__device__ float g_o2[(size_t)NB * NSEQ * CDIM];          // 8*1024*768   = 25 MB

// ---------------------------------------------------------------------------
// Generic tiled SGEMM: C[M,N] = alpha * A[M,K] @ B'[K,N] (+ bias[n])
//   TRANSB=false: B stored [K,N] row-major (ldb = N-stride)
//   TRANSB=true : B stored [N,K] row-major (ldb = K-stride)  (i.e. C = A @ B^T)
// Batched via blockIdx.z with split strides: z -> (zo = z/zdiv, zi = z%zdiv)
// ---------------------------------------------------------------------------
template<int BM, int BN, int BK, int TM, int TN, bool TRANSB, bool BIAS>
__global__ __launch_bounds__(256) void gemm_kernel(
    const float* __restrict__ A, const float* __restrict__ Bm,
    float* __restrict__ C, const float* __restrict__ bias,
    int M, int Nn, int K, int lda, int ldb, int ldc,
    int zdiv,
    long long sAo, long long sAi,
    long long sBo, long long sBi,
    long long sCo, long long sCi,
    float alpha)
{
    static_assert(BK == 16, "loader assumes BK==16");
    __shared__ float As[BM][BK + 1];   // +1 pad: conflict-free col-wise reads
    __shared__ float Bs[BK][BN + 4];   // +4 pad: tames TRANSB store conflicts

    {
        int z  = blockIdx.z;
        int zo = z / zdiv;
        int zi = z - zo * zdiv;
        A  += zo * sAo + zi * sAi;
        Bm += zo * sBo + zi * sBi;
        C  += zo * sCo + zi * sCi;
    }

    const int tid = threadIdx.x;
    const int m0  = blockIdx.y * BM;
    const int n0  = blockIdx.x * BN;
    const int tx  = tid & 15;       // 16 thread cols
    const int ty  = tid >> 4;       // 16 thread rows

    float acc[TM][TN];
    #pragma unroll
    for (int i = 0; i < TM; i++)
        #pragma unroll
        for (int j = 0; j < TN; j++)
            acc[i][j] = 0.f;

    for (int k0 = 0; k0 < K; k0 += BK) {
        // ---- load A tile (BM x BK), coalesced along k ----
        #pragma unroll
        for (int i = 0; i < (BM * BK) / 256; i++) {
            int idx = tid + i * 256;
            int m = idx >> 4;          // idx / BK
            int k = idx & 15;          // idx % BK
            As[m][k] = A[(long long)(m0 + m) * lda + (k0 + k)];
        }
        // ---- load B tile (BK x BN) ----
        if (TRANSB) {
            #pragma unroll
            for (int i = 0; i < (BN * BK) / 256; i++) {
                int idx = tid + i * 256;
                int n = idx >> 4;
                int k = idx & 15;
                Bs[k][n] = Bm[(long long)(n0 + n) * ldb + (k0 + k)];
            }
        } else {
            #pragma unroll
            for (int i = 0; i < (BN * BK) / 256; i++) {
                int idx = tid + i * 256;
                int k = idx / BN;
                int n = idx - k * BN;
                Bs[k][n] = Bm[(long long)(k0 + k) * ldb + (n0 + n)];
            }
        }
        __syncthreads();

        // ---- compute 8x4 per-thread outer products ----
        #pragma unroll
        for (int k = 0; k < BK; k++) {
            float a[TM], b[TN];
            #pragma unroll
            for (int i = 0; i < TM; i++) a[i] = As[ty * TM + i][k];
            #pragma unroll
            for (int j = 0; j < TN; j++) b[j] = Bs[k][tx * TN + j];
            #pragma unroll
            for (int i = 0; i < TM; i++)
                #pragma unroll
                for (int j = 0; j < TN; j++)
                    acc[i][j] += a[i] * b[j];
        }
        __syncthreads();
    }

    // ---- epilogue ----
    #pragma unroll
    for (int i = 0; i < TM; i++) {
        int m = m0 + ty * TM + i;
        #pragma unroll
        for (int j = 0; j < TN; j++) {
            int n = n0 + tx * TN + j;
            float v = acc[i][j] * alpha;
            if (BIAS) v += bias[n];
            C[(long long)m * ldc + n] = v;
        }
    }
}

// ---------------------------------------------------------------------------
// Fused: attn_row = softmax(scores_row * scale + bias_table[rel_index_row])
// one block (256 threads) per (b,h,n) row of 1024 elements
// ---------------------------------------------------------------------------
__global__ __launch_bounds__(256) void softmax_bias_kernel(
    float* __restrict__ attn,
    const float* __restrict__ bias_table,
    const int* __restrict__ rel_index,
    float scale)
{
    const int r  = blockIdx.x;            // r = bh*NSEQ + n
    const int n  = r & (NSEQ - 1);
    const int bh = r >> 10;
    const int h  = bh % NH;

    float* row = attn + (long long)r * NSEQ;
    const int* ridx = rel_index + (long long)n * NSEQ;
    const int tid = threadIdx.x;

    float v[4];
    float mx = -INFINITY;
    #pragma unroll
    for (int i = 0; i < 4; i++) {
        int m = tid + i * 256;
        float s = row[m] * scale + bias_table[ridx[m] * NH + h];
        v[i] = s;
        mx = fmaxf(mx, s);
    }

    __shared__ float red[8];
    #pragma unroll
    for (int off = 16; off > 0; off >>= 1)
        mx = fmaxf(mx, __shfl_xor_sync(0xffffffffu, mx, off));
    if ((tid & 31) == 0) red[tid >> 5] = mx;
    __syncthreads();
    mx = fmaxf(fmaxf(fmaxf(red[0], red[1]), fmaxf(red[2], red[3])),
               fmaxf(fmaxf(red[4], red[5]), fmaxf(red[6], red[7])));

    float sum = 0.f;
    #pragma unroll
    for (int i = 0; i < 4; i++) { v[i] = __expf(v[i] - mx); sum += v[i]; }
    #pragma unroll
    for (int off = 16; off > 0; off >>= 1)
        sum += __shfl_xor_sync(0xffffffffu, sum, off);
    __syncthreads();
    if ((tid & 31) == 0) red[tid >> 5] = sum;
    __syncthreads();
    sum = red[0] + red[1] + red[2] + red[3] + red[4] + red[5] + red[6] + red[7];

    float inv = 1.f / sum;
    #pragma unroll
    for (int i = 0; i < 4; i++)
        row[tid + i * 256] = v[i] * inv;
}

// ---------------------------------------------------------------------------
extern "C" void kernel_launch(void* const* d_in, const int* in_sizes, int n_in,
                              void* d_out, int out_size)
{
    const float* x          = (const float*)d_in[0];
    const float* qkv_w      = (const float*)d_in[1];
    const float* proj_w     = (const float*)d_in[2];
    const float* proj_b     = (const float*)d_in[3];
    const float* bias_table = (const float*)d_in[4];
    const int*   rel_index  = (const int*)d_in[5];
    float* out = (float*)d_out;

    float *qkv, *attn, *o2;
    cudaGetSymbolAddress((void**)&qkv,  g_qkv);
    cudaGetSymbolAddress((void**)&attn, g_attn);
    cudaGetSymbolAddress((void**)&o2,   g_o2);

    const dim3 blk(256);
    const long long sQKV = (long long)NSEQ * 3 * CDIM;    // per-batch qkv row stride
    const long long sATT = (long long)NSEQ * NSEQ;        // per-(b,h) attn stride

    // 1) qkv = x @ qkv_w : [8192,2304] = [8192,768] @ [768,2304]
    gemm_kernel<128, 64, 16, 8, 4, false, false>
        <<<dim3(3 * CDIM / 64, NB * NSEQ / 128, 1), blk>>>(
        x, qkv_w, qkv, nullptr,
        NB * NSEQ, 3 * CDIM, CDIM, CDIM, 3 * CDIM, 3 * CDIM,
        1, 0, 0, 0, 0, 0, 0, 1.f);

    // 2) S[bh] = Q[bh] @ K[bh]^T : 96 x [1024,1024,64]
    gemm_kernel<128, 64, 16, 8, 4, true, false>
        <<<dim3(NSEQ / 64, NSEQ / 128, NB * NH), blk>>>(
        qkv /*Q at col 0*/, qkv + CDIM /*K at col 768*/, attn, nullptr,
        NSEQ, NSEQ, HD, 3 * CDIM, 3 * CDIM, NSEQ,
        NH, sQKV, HD, sQKV, HD, (long long)NH * sATT, sATT, 1.f);

    // 3) softmax(S*scale + rel_bias)
    softmax_bias_kernel<<<NB * NH * NSEQ, 256>>>(attn, bias_table, rel_index, 0.125f);

    // 4) O2[bh] = P[bh] @ V[bh] : 96 x [1024,64,1024] -> packed [8192,768]
    gemm_kernel<128, 64, 16, 8, 4, false, false>
        <<<dim3(HD / 64, NSEQ / 128, NB * NH), blk>>>(
        attn, qkv + 2 * CDIM /*V at col 1536*/, o2, nullptr,
        NSEQ, HD, NSEQ, NSEQ, 3 * CDIM, CDIM,
        NH, (long long)NH * sATT, sATT, sQKV, HD, (long long)NSEQ * CDIM, HD, 1.f);

    // 5) out = O2 @ proj_w + proj_b : [8192,768]
    gemm_kernel<128, 64, 16, 8, 4, false, true>
        <<<dim3(CDIM / 64, NB * NSEQ / 128, 1), blk>>>(
        o2, proj_w, out, proj_b,
        NB * NSEQ, CDIM, CDIM, CDIM, CDIM, CDIM,
        1, 0, 0, 0, 0, 0, 0, 1.f);
}

// round 7
// speedup vs baseline: 1.0028x; 1.0001x over previous
#include <cuda_runtime.h>
#include <math.h>

#define NB   8
#define NSEQ 1024
#define CDIM 768
#define NH   12
#define HD   64

// Scratch (device globals: allocation-free per harness rules)
__device__ float g_qkv[(size_t)NB * NSEQ * 3 * CDIM];     // 8*1024*2304  = 75.5 MB
__device__ float g_attn[(size_t)NB * NH * NSEQ * NSEQ];   // 96*1024*1024 = 402 MB
__device__ float g_o2[(size_t)NB * NSEQ * CDIM];          // 8*1024*768   = 25 MB

// ---------------------------------------------------------------------------
// Generic tiled SGEMM: C[M,N] = alpha * A[M,K] @ B'[K,N] (+ bias[n])
//   TRANSB=false: B stored [K,N] row-major (ldb = N-stride)
//   TRANSB=true : B stored [N,K] row-major (ldb = K-stride)  (i.e. C = A @ B^T)
// Batched via blockIdx.z with split strides: z -> (zo = z/zdiv, zi = z%zdiv)
// ---------------------------------------------------------------------------
template<int BM, int BN, int BK, int TM, int TN, bool TRANSB, bool BIAS>
__global__ __launch_bounds__(256) void gemm_kernel(
    const float* __restrict__ A, const float* __restrict__ Bm,
    float* __restrict__ C, const float* __restrict__ bias,
    int M, int Nn, int K, int lda, int ldb, int ldc,
    int zdiv,
    long long sAo, long long sAi,
    long long sBo, long long sBi,
    long long sCo, long long sCi,
    float alpha)
{
    static_assert(BK == 16, "loader assumes BK==16");
    __shared__ float As[BM][BK + 1];   // +1 pad: conflict-free col-wise reads
    __shared__ float Bs[BK][BN + 4];   // +4 pad: tames TRANSB store conflicts

    {
        int z  = blockIdx.z;
        int zo = z / zdiv;
        int zi = z - zo * zdiv;
        A  += zo * sAo + zi * sAi;
        Bm += zo * sBo + zi * sBi;
        C  += zo * sCo + zi * sCi;
    }

    const int tid = threadIdx.x;
    const int m0  = blockIdx.y * BM;
    const int n0  = blockIdx.x * BN;
    const int tx  = tid & 15;       // 16 thread cols
    const int ty  = tid >> 4;       // 16 thread rows

    float acc[TM][TN];
    #pragma unroll
    for (int i = 0; i < TM; i++)
        #pragma unroll
        for (int j = 0; j < TN; j++)
            acc[i][j] = 0.f;

    for (int k0 = 0; k0 < K; k0 += BK) {
        // ---- load A tile (BM x BK), coalesced along k ----
        #pragma unroll
        for (int i = 0; i < (BM * BK) / 256; i++) {
            int idx = tid + i * 256;
            int m = idx >> 4;          // idx / BK
            int k = idx & 15;          // idx % BK
            As[m][k] = A[(long long)(m0 + m) * lda + (k0 + k)];
        }
        // ---- load B tile (BK x BN) ----
        if (TRANSB) {
            #pragma unroll
            for (int i = 0; i < (BN * BK) / 256; i++) {
                int idx = tid + i * 256;
                int n = idx >> 4;
                int k = idx & 15;
                Bs[k][n] = Bm[(long long)(n0 + n) * ldb + (k0 + k)];
            }
        } else {
            #pragma unroll
            for (int i = 0; i < (BN * BK) / 256; i++) {
                int idx = tid + i * 256;
                int k = idx / BN;
                int n = idx - k * BN;
                Bs[k][n] = Bm[(long long)(k0 + k) * ldb + (n0 + n)];
            }
        }
        __syncthreads();

        // ---- compute 8x4 per-thread outer products ----
        #pragma unroll
        for (int k = 0; k < BK; k++) {
            float a[TM], b[TN];
            #pragma unroll
            for (int i = 0; i < TM; i++) a[i] = As[ty * TM + i][k];
            #pragma unroll
            for (int j = 0; j < TN; j++) b[j] = Bs[k][tx * TN + j];
            #pragma unroll
            for (int i = 0; i < TM; i++)
                #pragma unroll
                for (int j = 0; j < TN; j++)
                    acc[i][j] += a[i] * b[j];
        }
        __syncthreads();
    }

    // ---- epilogue ----
    #pragma unroll
    for (int i = 0; i < TM; i++) {
        int m = m0 + ty * TM + i;
        #pragma unroll
        for (int j = 0; j < TN; j++) {
            int n = n0 + tx * TN + j;
            float v = acc[i][j] * alpha;
            if (BIAS) v += bias[n];
            C[(long long)m * ldc + n] = v;
        }
    }
}

// ---------------------------------------------------------------------------
// Fused: attn_row = softmax(scores_row * scale + bias_table[rel_index_row])
// one block (256 threads) per (b,h,n) row of 1024 elements
// ---------------------------------------------------------------------------
__global__ __launch_bounds__(256) void softmax_bias_kernel(
    float* __restrict__ attn,
    const float* __restrict__ bias_table,
    const int* __restrict__ rel_index,
    float scale)
{
    const int r  = blockIdx.x;            // r = bh*NSEQ + n
    const int n  = r & (NSEQ - 1);
    const int bh = r >> 10;
    const int h  = bh % NH;

    float* row = attn + (long long)r * NSEQ;
    const int* ridx = rel_index + (long long)n * NSEQ;
    const int tid = threadIdx.x;

    float v[4];
    float mx = -INFINITY;
    #pragma unroll
    for (int i = 0; i < 4; i++) {
        int m = tid + i * 256;
        float s = row[m] * scale + bias_table[ridx[m] * NH + h];
        v[i] = s;
        mx = fmaxf(mx, s);
    }

    __shared__ float red[8];
    #pragma unroll
    for (int off = 16; off > 0; off >>= 1)
        mx = fmaxf(mx, __shfl_xor_sync(0xffffffffu, mx, off));
    if ((tid & 31) == 0) red[tid >> 5] = mx;
    __syncthreads();
    mx = fmaxf(fmaxf(fmaxf(red[0], red[1]), fmaxf(red[2], red[3])),
               fmaxf(fmaxf(red[4], red[5]), fmaxf(red[6], red[7])));

    float sum = 0.f;
    #pragma unroll
    for (int i = 0; i < 4; i++) { v[i] = __expf(v[i] - mx); sum += v[i]; }
    #pragma unroll
    for (int off = 16; off > 0; off >>= 1)
        sum += __shfl_xor_sync(0xffffffffu, sum, off);
    __syncthreads();
    if ((tid & 31) == 0) red[tid >> 5] = sum;
    __syncthreads();
    sum = red[0] + red[1] + red[2] + red[3] + red[4] + red[5] + red[6] + red[7];

    float inv = 1.f / sum;
    #pragma unroll
    for (int i = 0; i < 4; i++)
        row[tid + i * 256] = v[i] * inv;
}

// ---------------------------------------------------------------------------
extern "C" void kernel_launch(void* const* d_in, const int* in_sizes, int n_in,
                              void* d_out, int out_size)
{
    const float* x          = (const float*)d_in[0];
    const float* qkv_w      = (const float*)d_in[1];
    const float* proj_w     = (const float*)d_in[2];
    const float* proj_b     = (const float*)d_in[3];
    const float* bias_table = (const float*)d_in[4];
    const int*   rel_index  = (const int*)d_in[5];
    float* out = (float*)d_out;

    float *qkv, *attn, *o2;
    cudaGetSymbolAddress((void**)&qkv,  g_qkv);
    cudaGetSymbolAddress((void**)&attn, g_attn);
    cudaGetSymbolAddress((void**)&o2,   g_o2);

    const dim3 blk(256);
    const long long sQKV = (long long)NSEQ * 3 * CDIM;    // per-batch qkv row stride
    const long long sATT = (long long)NSEQ * NSEQ;        // per-(b,h) attn stride

    // 1) qkv = x @ qkv_w : [8192,2304] = [8192,768] @ [768,2304]
    gemm_kernel<128, 64, 16, 8, 4, false, false>
        <<<dim3(3 * CDIM / 64, NB * NSEQ / 128, 1), blk>>>(
        x, qkv_w, qkv, nullptr,
        NB * NSEQ, 3 * CDIM, CDIM, CDIM, 3 * CDIM, 3 * CDIM,
        1, 0, 0, 0, 0, 0, 0, 1.f);

    // 2) S[bh] = Q[bh] @ K[bh]^T : 96 x [1024,1024,64]
    gemm_kernel<128, 64, 16, 8, 4, true, false>
        <<<dim3(NSEQ / 64, NSEQ / 128, NB * NH), blk>>>(
        qkv /*Q at col 0*/, qkv + CDIM /*K at col 768*/, attn, nullptr,
        NSEQ, NSEQ, HD, 3 * CDIM, 3 * CDIM, NSEQ,
        NH, sQKV, HD, sQKV, HD, (long long)NH * sATT, sATT, 1.f);

    // 3) softmax(S*scale + rel_bias)
    softmax_bias_kernel<<<NB * NH * NSEQ, 256>>>(attn, bias_table, rel_index, 0.125f);

    // 4) O2[bh] = P[bh] @ V[bh] : 96 x [1024,64,1024] -> packed [8192,768]
    gemm_kernel<128, 64, 16, 8, 4, false, false>
        <<<dim3(HD / 64, NSEQ / 128, NB * NH), blk>>>(
        attn, qkv + 2 * CDIM /*V at col 1536*/, o2, nullptr,
        NSEQ, HD, NSEQ, NSEQ, 3 * CDIM, CDIM,
        NH, (long long)NH * sATT, sATT, sQKV, HD, (long long)NSEQ * CDIM, HD, 1.f);

    // 5) out = O2 @ proj_w + proj_b : [8192,768]
    gemm_kernel<128, 64, 16, 8, 4, false, true>
        <<<dim3(CDIM / 64, NB * NSEQ / 128, 1), blk>>>(
        o2, proj_w, out, proj_b,
        NB * NSEQ, CDIM, CDIM, CDIM, CDIM, CDIM,
        1, 0, 0, 0, 0, 0, 0, 1.f);
}